// round 12
// baseline (speedup 1.0000x reference)
#include <cuda_runtime.h>
#include <cuda_bf16.h>
#include <cstdint>

#define NUM_GRAPHS 512
#define C 128
#define CG (C / 4)           // 32 channel-groups of float4
#define THREADS 512
#define RPI (THREADS / CG)   // 16 rows per iteration
#define EPS 1e-5f
#define GRID 256
#define NPAIRS (GRID / 2)               // 128 clusters of 2
#define NSEG (NUM_GRAPHS / NPAIRS)      // 4 segments per cluster

__device__ __forceinline__ uint32_t smem_u32(const void* p) {
    uint32_t a;
    asm("{ .reg .u64 t; cvta.to.shared.u64 t, %1; cvt.u32.u64 %0, t; }"
        : "=r"(a) : "l"(p));
    return a;
}
__device__ __forceinline__ uint32_t mapa_rank(uint32_t addr, uint32_t rank) {
    uint32_t r;
    asm("mapa.shared::cluster.u32 %0, %1, %2;" : "=r"(r) : "r"(addr), "r"(rank));
    return r;
}
__device__ __forceinline__ void st_dsmem_f32(uint32_t addr, float v) {
    asm volatile("st.shared::cluster.f32 [%0], %1;" :: "r"(addr), "f"(v) : "memory");
}
__device__ __forceinline__ void mbar_arrive_release_cluster(uint32_t addr) {
    asm volatile("mbarrier.arrive.release.cluster.shared::cluster.b64 _, [%0];"
                 :: "r"(addr) : "memory");
}
__device__ __forceinline__ void mbar_wait_parity_cluster(uint32_t addr, uint32_t par) {
    uint32_t done;
    do {
        asm volatile(
            "{\n\t.reg .pred p;\n\t"
            "mbarrier.try_wait.parity.acquire.cluster.shared::cta.b64 p, [%1], %2;\n\t"
            "selp.b32 %0, 1, 0, p;\n\t}"
            : "=r"(done) : "r"(addr), "r"(par) : "memory");
    } while (!done);
}
#define CLUSTER_SYNC() do { \
    asm volatile("barrier.cluster.arrive.aligned;" ::: "memory"); \
    asm volatile("barrier.cluster.wait.aligned;"   ::: "memory"); } while (0)

// Interpolation-guess + gallop partition-point search: first idx with batch[idx] >= g.
__device__ __forceinline__ int find_bound(const int* __restrict__ batch, int n, int g) {
    if (g <= 0) return 0;
    int p = (int)(((long long)g * (long long)n) >> 9);   // g*n/512 guess
    if (p > n) p = n;
    int wlo = p, s = 512;
    while (wlo > 0 && batch[wlo - 1] >= g) { wlo -= s; if (wlo < 0) wlo = 0; s <<= 1; }
    int whi = p; s = 512;
    while (whi < n && batch[whi] < g)      { whi += s; if (whi > n) whi = n; s <<= 1; }
    while (wlo < whi) {
        int mid = (wlo + whi) >> 1;
        if (batch[mid] < g) wlo = mid + 1; else whi = mid;
    }
    return wlo;
}

#define ACC(v) do { \
    s0 += (v).x; s1 += (v).y; s2 += (v).z; s3 += (v).w; \
    q0 += (v).x * (v).x; q1 += (v).y * (v).y; \
    q2 += (v).z * (v).z; q3 += (v).w * (v).w; } while (0)

#define NORM_ST(v, idx) do { \
    (v).x = ((v).x - m.x) * iv.x * wv.x + bv.x; \
    (v).y = ((v).y - m.y) * iv.y * wv.y + bv.y; \
    (v).z = ((v).z - m.z) * iv.z * wv.z + bv.z; \
    (v).w = ((v).w - m.w) * iv.w * wv.w + bv.w; \
    __stcs(&op[(size_t)(idx) * CG + cg], (v)); } while (0)

__global__ __launch_bounds__(THREADS, 2) __cluster_dims__(2, 1, 1)
void graphnorm_kernel(const float* __restrict__ x,
                      const int*   __restrict__ batch,
                      const float* __restrict__ weight,
                      const float* __restrict__ bias,
                      float* __restrict__ out,
                      int n) {
    const int t    = threadIdx.x;
    const int cg   = t & (CG - 1);
    const int rw   = t >> 5;
    const int rank = blockIdx.x & 1;
    const int pair = blockIdx.x >> 1;

    __shared__ int   s_bound[2 * NSEG];
    __shared__ float s_sum[RPI][C];
    __shared__ float s_sq [RPI][C];
    __shared__ float s_recv[2][2][C];        // [parity][sum|sq][C], written by PEER
    __shared__ float s_mean[C];
    __shared__ float s_inv [C];
    __shared__ alignas(8) unsigned long long s_mbar;

    if (t < 2 * NSEG) {
        const int g = pair + (t >> 1) * NPAIRS + (t & 1);
        s_bound[t] = find_bound(batch, n, g);
    }
    const uint32_t mbar_local = smem_u32(&s_mbar);
    if (t == 0) {
        asm volatile("mbarrier.init.shared.b64 [%0], %1;"
                     :: "r"(mbar_local), "r"(32u) : "memory");
    }

    const float4 wv = ((const float4*)weight)[cg];
    const float4 bv = ((const float4*)bias)[cg];
    const float4* __restrict__ xp = (const float4*)x;
    float4* __restrict__       op = (float4*)out;

    const uint32_t recv_local = smem_u32(&s_recv[0][0][0]);
    const uint32_t recv_peer  = mapa_rank(recv_local, rank ^ 1);
    const uint32_t mbar_peer  = mapa_rank(mbar_local, rank ^ 1);

    __syncthreads();
    CLUSTER_SYNC();   // peer mbarrier init visible before first push

    // half-range of segment i for this CTA
    auto half_lo = [&](int i) {
        int st = s_bound[2 * i], en = s_bound[2 * i + 1];
        int mid = st + ((en - st) >> 1);
        return rank ? mid : st;
    };
    auto half_hi = [&](int i) {
        int st = s_bound[2 * i], en = s_bound[2 * i + 1];
        int mid = st + ((en - st) >> 1);
        return rank ? en : mid;
    };

    float s0, s1, s2, s3, q0, q1, q2, q3;

    // ======== prologue: P1(seg 0), unfused, 4-unroll ========
    {
        const int h0 = half_lo(0), h1 = half_hi(0);
        s0 = s1 = s2 = s3 = q0 = q1 = q2 = q3 = 0.f;
        int r = h0 + rw;
        for (; r + 3 * RPI < h1; r += 4 * RPI) {
            float4 a = xp[(size_t)r * CG + cg];
            float4 b = xp[(size_t)(r + 1 * RPI) * CG + cg];
            float4 c = xp[(size_t)(r + 2 * RPI) * CG + cg];
            float4 d = xp[(size_t)(r + 3 * RPI) * CG + cg];
            ACC(a); ACC(b); ACC(c); ACC(d);
        }
        for (; r < h1; r += RPI) { float4 v = xp[(size_t)r * CG + cg]; ACC(v); }
    }

    for (int i = 0; i < NSEG; i++) {
        // ---- store partials, exchange with peer, combine -> s_mean/s_inv ----
        s_sum[rw][cg * 4 + 0] = s0; s_sum[rw][cg * 4 + 1] = s1;
        s_sum[rw][cg * 4 + 2] = s2; s_sum[rw][cg * 4 + 3] = s3;
        s_sq [rw][cg * 4 + 0] = q0; s_sq [rw][cg * 4 + 1] = q1;
        s_sq [rw][cg * 4 + 2] = q2; s_sq [rw][cg * 4 + 3] = q3;
        __syncthreads();

        const int par = i & 1;
        const int cnt = s_bound[2 * i + 1] - s_bound[2 * i];
        if (rw == 0) {
            float S0 = 0.f, S1 = 0.f, S2 = 0.f, S3 = 0.f;
            float Q0 = 0.f, Q1 = 0.f, Q2 = 0.f, Q3 = 0.f;
            #pragma unroll
            for (int k = 0; k < RPI; k++) {
                S0 += s_sum[k][cg * 4 + 0]; S1 += s_sum[k][cg * 4 + 1];
                S2 += s_sum[k][cg * 4 + 2]; S3 += s_sum[k][cg * 4 + 3];
                Q0 += s_sq [k][cg * 4 + 0]; Q1 += s_sq [k][cg * 4 + 1];
                Q2 += s_sq [k][cg * 4 + 2]; Q3 += s_sq [k][cg * 4 + 3];
            }
            const uint32_t dst = recv_peer + (uint32_t)par * (2 * C * 4)
                                           + (uint32_t)cg * 16u;
            st_dsmem_f32(dst +  0, S0); st_dsmem_f32(dst +  4, S1);
            st_dsmem_f32(dst +  8, S2); st_dsmem_f32(dst + 12, S3);
            st_dsmem_f32(dst + C * 4 +  0, Q0); st_dsmem_f32(dst + C * 4 +  4, Q1);
            st_dsmem_f32(dst + C * 4 +  8, Q2); st_dsmem_f32(dst + C * 4 + 12, Q3);
            mbar_arrive_release_cluster(mbar_peer);
            mbar_wait_parity_cluster(mbar_local, (uint32_t)par);

            float P0 = s_recv[par][0][cg * 4 + 0], P1x = s_recv[par][0][cg * 4 + 1];
            float P2x = s_recv[par][0][cg * 4 + 2], P3 = s_recv[par][0][cg * 4 + 3];
            float R0 = s_recv[par][1][cg * 4 + 0], R1 = s_recv[par][1][cg * 4 + 1];
            float R2 = s_recv[par][1][cg * 4 + 2], R3 = s_recv[par][1][cg * 4 + 3];

            const float invc = 1.0f / (float)max(cnt, 1);
            float m0 = (S0 + P0) * invc, m1 = (S1 + P1x) * invc;
            float m2 = (S2 + P2x) * invc, m3 = (S3 + P3) * invc;
            float v0 = (Q0 + R0) * invc - m0 * m0;
            float v1 = (Q1 + R1) * invc - m1 * m1;
            float v2 = (Q2 + R2) * invc - m2 * m2;
            float v3 = (Q3 + R3) * invc - m3 * m3;
            s_mean[cg * 4 + 0] = m0; s_mean[cg * 4 + 1] = m1;
            s_mean[cg * 4 + 2] = m2; s_mean[cg * 4 + 3] = m3;
            s_inv [cg * 4 + 0] = rsqrtf(v0 + EPS);
            s_inv [cg * 4 + 1] = rsqrtf(v1 + EPS);
            s_inv [cg * 4 + 2] = rsqrtf(v2 + EPS);
            s_inv [cg * 4 + 3] = rsqrtf(v3 + EPS);
        }
        __syncthreads();

        const float4 m  = ((const float4*)s_mean)[cg];
        const float4 iv = ((const float4*)s_inv)[cg];

        // prev-segment normalize range (segment i), this CTA's half
        const int p0 = half_lo(i), p1 = half_hi(i);
        int r2 = p0 + rw;

        if (i + 1 < NSEG) {
            // ======== fused window: P2(seg i) + P1(seg i+1) ========
            const int c0 = half_lo(i + 1), c1 = half_hi(i + 1);
            int r1 = c0 + rw;
            s0 = s1 = s2 = s3 = q0 = q1 = q2 = q3 = 0.f;

            // 2+2 interleave: 2 DRAM reads (next seg) + 2 L2 reads + 2 streaming stores
            while (r1 + RPI < c1 && r2 + RPI < p1) {
                float4 a = xp[(size_t)r1 * CG + cg];
                float4 b = xp[(size_t)(r1 + RPI) * CG + cg];
                float4 u = __ldcs(&xp[(size_t)r2 * CG + cg]);
                float4 w = __ldcs(&xp[(size_t)(r2 + RPI) * CG + cg]);
                ACC(a); ACC(b);
                NORM_ST(u, r2); NORM_ST(w, r2 + RPI);
                r1 += 2 * RPI; r2 += 2 * RPI;
            }
            while (r1 < c1 && r2 < p1) {
                float4 a = xp[(size_t)r1 * CG + cg];
                float4 u = __ldcs(&xp[(size_t)r2 * CG + cg]);
                ACC(a);
                NORM_ST(u, r2);
                r1 += RPI; r2 += RPI;
            }
            for (; r1 < c1; r1 += RPI) { float4 a = xp[(size_t)r1 * CG + cg]; ACC(a); }
            for (; r2 < p1; r2 += RPI) {
                float4 u = __ldcs(&xp[(size_t)r2 * CG + cg]);
                NORM_ST(u, r2);
            }
        } else {
            // ======== epilogue: P2(seg NSEG-1), unfused ========
            for (; r2 + RPI < p1; r2 += 2 * RPI) {
                float4 u = __ldcs(&xp[(size_t)r2 * CG + cg]);
                float4 w = __ldcs(&xp[(size_t)(r2 + RPI) * CG + cg]);
                NORM_ST(u, r2); NORM_ST(w, r2 + RPI);
            }
            for (; r2 < p1; r2 += RPI) {
                float4 u = __ldcs(&xp[(size_t)r2 * CG + cg]);
                NORM_ST(u, r2);
            }
        }
        __syncthreads();   // protect s_sum/s_mean before next iteration's writes
    }

    CLUSTER_SYNC();   // don't exit while peer may still target my smem
}

extern "C" void kernel_launch(void* const* d_in, const int* in_sizes, int n_in,
                              void* d_out, int out_size) {
    const float* x      = (const float*)d_in[0];
    const int*   batch  = (const int*)d_in[1];
    const float* weight = (const float*)d_in[2];
    const float* bias   = (const float*)d_in[3];
    float*       out    = (float*)d_out;
    const int n = in_sizes[1];

    graphnorm_kernel<<<GRID, THREADS>>>(x, batch, weight, bias, out, n);
}

// round 13
// speedup vs baseline: 1.1210x; 1.1210x over previous
#include <cuda_runtime.h>
#include <cuda_bf16.h>
#include <cstdint>

#define NUM_GRAPHS 512
#define C 128
#define CG (C / 4)           // 32 channel-groups of float4
#define THREADS 512
#define RPI (THREADS / CG)   // 16 rows per iteration
#define EPS 1e-5f
#define GRID 256
#define NPAIRS (GRID / 2)               // 128 clusters of 2
#define NSEG (NUM_GRAPHS / NPAIRS)      // 4 segments per cluster
#define DEPTH 8                          // cp.async ring slots per thread
#define RING_BYTES (THREADS * DEPTH * 16)   // 64 KB dynamic smem

extern __shared__ float4 g_ring[];   // [DEPTH][THREADS] float4, slot-major

__device__ __forceinline__ uint32_t smem_u32(const void* p) {
    uint32_t a;
    asm("{ .reg .u64 t; cvta.to.shared.u64 t, %1; cvt.u32.u64 %0, t; }"
        : "=r"(a) : "l"(p));
    return a;
}
__device__ __forceinline__ uint32_t mapa_rank(uint32_t addr, uint32_t rank) {
    uint32_t r;
    asm("mapa.shared::cluster.u32 %0, %1, %2;" : "=r"(r) : "r"(addr), "r"(rank));
    return r;
}
__device__ __forceinline__ void st_dsmem_f32(uint32_t addr, float v) {
    asm volatile("st.shared::cluster.f32 [%0], %1;" :: "r"(addr), "f"(v) : "memory");
}
__device__ __forceinline__ void mbar_arrive_release_cluster(uint32_t addr) {
    asm volatile("mbarrier.arrive.release.cluster.shared::cluster.b64 _, [%0];"
                 :: "r"(addr) : "memory");
}
__device__ __forceinline__ void mbar_wait_parity_cluster(uint32_t addr, uint32_t par) {
    uint32_t done;
    do {
        asm volatile(
            "{\n\t.reg .pred p;\n\t"
            "mbarrier.try_wait.parity.acquire.cluster.shared::cta.b64 p, [%1], %2;\n\t"
            "selp.b32 %0, 1, 0, p;\n\t}"
            : "=r"(done) : "r"(addr), "r"(par) : "memory");
    } while (!done);
}
#define CLUSTER_SYNC() do { \
    asm volatile("barrier.cluster.arrive.aligned;" ::: "memory"); \
    asm volatile("barrier.cluster.wait.aligned;"   ::: "memory"); } while (0)

__device__ __forceinline__ void cp_async16(uint32_t saddr, const void* gaddr) {
    asm volatile("cp.async.cg.shared.global [%0], [%1], 16;"
                 :: "r"(saddr), "l"(gaddr) : "memory");
}
__device__ __forceinline__ void cp_commit() {
    asm volatile("cp.async.commit_group;" ::: "memory");
}
__device__ __forceinline__ void cp_wait_d1() {
    asm volatile("cp.async.wait_group %0;" :: "n"(DEPTH - 1) : "memory");
}

// Interpolation-guess + gallop: first idx with batch[idx] >= g.
__device__ __forceinline__ int find_bound(const int* __restrict__ batch, int n, int g) {
    if (g <= 0) return 0;
    int p = (int)(((long long)g * (long long)n) >> 9);
    if (p > n) p = n;
    int wlo = p, s = 512;
    while (wlo > 0 && batch[wlo - 1] >= g) { wlo -= s; if (wlo < 0) wlo = 0; s <<= 1; }
    int whi = p; s = 512;
    while (whi < n && batch[whi] < g)      { whi += s; if (whi > n) whi = n; s <<= 1; }
    while (wlo < whi) {
        int mid = (wlo + whi) >> 1;
        if (batch[mid] < g) wlo = mid + 1; else whi = mid;
    }
    return wlo;
}

#define ACC(v) do { \
    s0 += (v).x; s1 += (v).y; s2 += (v).z; s3 += (v).w; \
    q0 += (v).x * (v).x; q1 += (v).y * (v).y; \
    q2 += (v).z * (v).z; q3 += (v).w * (v).w; } while (0)

#define NORM_ST(v, idx) do { \
    (v).x = ((v).x - m.x) * iv.x * wv.x + bv.x; \
    (v).y = ((v).y - m.y) * iv.y * wv.y + bv.y; \
    (v).z = ((v).z - m.z) * iv.z * wv.z + bv.z; \
    (v).w = ((v).w - m.w) * iv.w * wv.w + bv.w; \
    __stcs(&op[(size_t)(idx) * CG + cg], (v)); } while (0)

__global__ __launch_bounds__(THREADS, 2) __cluster_dims__(2, 1, 1)
void graphnorm_kernel(const float* __restrict__ x,
                      const int*   __restrict__ batch,
                      const float* __restrict__ weight,
                      const float* __restrict__ bias,
                      float* __restrict__ out,
                      int n) {
    const int t    = threadIdx.x;
    const int cg   = t & (CG - 1);
    const int rw   = t >> 5;
    const int rank = blockIdx.x & 1;
    const int pair = blockIdx.x >> 1;

    __shared__ int   s_bound[2 * NSEG];
    __shared__ float s_sum[RPI][C];          // 8 KB
    __shared__ float s_sq [RPI][C];          // 8 KB
    __shared__ float s_recv[2][2][C];        // [parity][sum|sq][C], written by PEER
    __shared__ float s_mean[C];
    __shared__ float s_inv [C];
    __shared__ alignas(8) unsigned long long s_mbar;

    if (t < 2 * NSEG) {
        const int g = pair + (t >> 1) * NPAIRS + (t & 1);
        s_bound[t] = find_bound(batch, n, g);
    }
    const uint32_t mbar_local = smem_u32(&s_mbar);
    if (t == 0) {
        asm volatile("mbarrier.init.shared.b64 [%0], %1;"
                     :: "r"(mbar_local), "r"(32u) : "memory");
    }

    const float4 wv = ((const float4*)weight)[cg];
    const float4 bv = ((const float4*)bias)[cg];
    const float4* __restrict__ xp = (const float4*)x;
    float4* __restrict__       op = (float4*)out;

    const uint32_t recv_local = smem_u32(&s_recv[0][0][0]);
    const uint32_t recv_peer  = mapa_rank(recv_local, rank ^ 1);
    const uint32_t mbar_peer  = mapa_rank(mbar_local, rank ^ 1);

    // per-thread ring slots, slot-major: slot s at ring_base + (s*THREADS + t)*16
    const uint32_t ring_t = smem_u32(g_ring) + (uint32_t)t * 16u;

    __syncthreads();
    CLUSTER_SYNC();   // peer mbarrier init visible before first push

    for (int i = 0; i < NSEG; i++) {
        const int start = s_bound[2 * i];
        const int end   = s_bound[2 * i + 1];
        const int cnt   = end - start;
        const int smid  = start + (cnt >> 1);
        const int h0    = rank ? smid : start;   // this CTA's half
        const int h1    = rank ? end  : smid;

        // ---- pass 1: cp.async ring over OWN half; zero barriers in the loop ----
        float s0 = 0.f, s1 = 0.f, s2 = 0.f, s3 = 0.f;
        float q0 = 0.f, q1 = 0.f, q2 = 0.f, q3 = 0.f;
        {
            const int r0  = h0 + rw;
            const int nIt = (h1 > r0) ? ((h1 - r0 + RPI - 1) / RPI) : 0;
            const float4* gp = xp + (size_t)r0 * CG + cg;   // step RPI*CG per item

            // prologue: issue up to DEPTH items, one group each (uniform count)
            #pragma unroll
            for (int d = 0; d < DEPTH; d++) {
                if (d < nIt)
                    cp_async16(ring_t + (uint32_t)d * (THREADS * 16),
                               gp + (size_t)d * (RPI * CG));
                cp_commit();
            }
            // steady state: wait oldest, consume own slot, refill, commit
            for (int j = 0; j < nIt; j++) {
                cp_wait_d1();
                const int sl = j & (DEPTH - 1);
                float4 v = g_ring[sl * THREADS + t];
                ACC(v);
                const int f = j + DEPTH;
                if (f < nIt)
                    cp_async16(ring_t + (uint32_t)sl * (THREADS * 16),
                               gp + (size_t)f * (RPI * CG));
                cp_commit();
            }
        }
        s_sum[rw][cg * 4 + 0] = s0; s_sum[rw][cg * 4 + 1] = s1;
        s_sum[rw][cg * 4 + 2] = s2; s_sum[rw][cg * 4 + 3] = s3;
        s_sq [rw][cg * 4 + 0] = q0; s_sq [rw][cg * 4 + 1] = q1;
        s_sq [rw][cg * 4 + 2] = q2; s_sq [rw][cg * 4 + 3] = q3;
        __syncthreads();

        // ---- warp 0: reduce, push partials to peer, wait for peer's, combine ----
        const int par = i & 1;
        if (rw == 0) {
            float S0 = 0.f, S1 = 0.f, S2 = 0.f, S3 = 0.f;
            float Q0 = 0.f, Q1 = 0.f, Q2 = 0.f, Q3 = 0.f;
            #pragma unroll
            for (int k = 0; k < RPI; k++) {
                S0 += s_sum[k][cg * 4 + 0]; S1 += s_sum[k][cg * 4 + 1];
                S2 += s_sum[k][cg * 4 + 2]; S3 += s_sum[k][cg * 4 + 3];
                Q0 += s_sq [k][cg * 4 + 0]; Q1 += s_sq [k][cg * 4 + 1];
                Q2 += s_sq [k][cg * 4 + 2]; Q3 += s_sq [k][cg * 4 + 3];
            }
            const uint32_t dst = recv_peer + (uint32_t)par * (2 * C * 4)
                                           + (uint32_t)cg * 16u;
            st_dsmem_f32(dst +  0, S0); st_dsmem_f32(dst +  4, S1);
            st_dsmem_f32(dst +  8, S2); st_dsmem_f32(dst + 12, S3);
            st_dsmem_f32(dst + C * 4 +  0, Q0); st_dsmem_f32(dst + C * 4 +  4, Q1);
            st_dsmem_f32(dst + C * 4 +  8, Q2); st_dsmem_f32(dst + C * 4 + 12, Q3);
            mbar_arrive_release_cluster(mbar_peer);
            mbar_wait_parity_cluster(mbar_local, (uint32_t)par);

            float P0 = s_recv[par][0][cg * 4 + 0], P1 = s_recv[par][0][cg * 4 + 1];
            float P2 = s_recv[par][0][cg * 4 + 2], P3 = s_recv[par][0][cg * 4 + 3];
            float R0 = s_recv[par][1][cg * 4 + 0], R1 = s_recv[par][1][cg * 4 + 1];
            float R2 = s_recv[par][1][cg * 4 + 2], R3 = s_recv[par][1][cg * 4 + 3];

            const float invc = 1.0f / (float)max(cnt, 1);
            float m0 = (S0 + P0) * invc, m1 = (S1 + P1) * invc;
            float m2 = (S2 + P2) * invc, m3 = (S3 + P3) * invc;
            float v0 = (Q0 + R0) * invc - m0 * m0;
            float v1 = (Q1 + R1) * invc - m1 * m1;
            float v2 = (Q2 + R2) * invc - m2 * m2;
            float v3 = (Q3 + R3) * invc - m3 * m3;
            s_mean[cg * 4 + 0] = m0; s_mean[cg * 4 + 1] = m1;
            s_mean[cg * 4 + 2] = m2; s_mean[cg * 4 + 3] = m3;
            s_inv [cg * 4 + 0] = rsqrtf(v0 + EPS);
            s_inv [cg * 4 + 1] = rsqrtf(v1 + EPS);
            s_inv [cg * 4 + 2] = rsqrtf(v2 + EPS);
            s_inv [cg * 4 + 3] = rsqrtf(v3 + EPS);
        }
        __syncthreads();

        const float4 m  = ((const float4*)s_mean)[cg];
        const float4 iv = ((const float4*)s_inv)[cg];

        // ---- pass 2: normalize OWN half (L2-hot); 4-wide, evict-first + streaming ----
        int r = h0 + rw;
        for (; r + 3 * RPI < h1; r += 4 * RPI) {
            float4 a = __ldcs(&xp[(size_t)r * CG + cg]);
            float4 b = __ldcs(&xp[(size_t)(r + 1 * RPI) * CG + cg]);
            float4 c = __ldcs(&xp[(size_t)(r + 2 * RPI) * CG + cg]);
            float4 d = __ldcs(&xp[(size_t)(r + 3 * RPI) * CG + cg]);
            NORM_ST(a, r);
            NORM_ST(b, r + 1 * RPI);
            NORM_ST(c, r + 2 * RPI);
            NORM_ST(d, r + 3 * RPI);
        }
        for (; r < h1; r += RPI) {
            float4 v = __ldcs(&xp[(size_t)r * CG + cg]);
            NORM_ST(v, r);
        }
        __syncthreads();   // protect s_sum/s_mean before next iteration's writes
    }

    CLUSTER_SYNC();   // don't exit while peer may still target my smem
}

extern "C" void kernel_launch(void* const* d_in, const int* in_sizes, int n_in,
                              void* d_out, int out_size) {
    const float* x      = (const float*)d_in[0];
    const int*   batch  = (const int*)d_in[1];
    const float* weight = (const float*)d_in[2];
    const float* bias   = (const float*)d_in[3];
    float*       out    = (float*)d_out;
    const int n = in_sizes[1];

    cudaFuncSetAttribute(graphnorm_kernel,
                         cudaFuncAttributeMaxDynamicSharedMemorySize, RING_BYTES);
    graphnorm_kernel<<<GRID, THREADS, RING_BYTES>>>(x, batch, weight, bias, out, n);
}